// round 4
// baseline (speedup 1.0000x reference)
#include <cuda_runtime.h>
#include <cuda_bf16.h>

// Problem constants (fixed by the reference)
#define NND   100000      // nodes
#define NED   50000       // hyperedges
#define NNZE  1280000     // incidence nnz
#define FT    128
#define HID   64
#define NCLS  32
#define NGR   256

#define XSTR  68          // padded shared row stride (floats)
#define NB_N  1563        // ceil(NND/64)
#define NB_E  782         // ceil(NED/64)

// ---------------- device scratch (static; no allocation allowed) -------------
__device__ float g_x   [NND * HID];
__device__ float g_x0  [NND * HID];
__device__ float g_esum[NED * HID];
__device__ float g_y   [NED * HID];
__device__ float g_cls [NND * NCLS];
__device__ int   g_ecnt[NED];
__device__ int   g_noff[NND + 1];
__device__ int   g_goff[NGR + 1];

// ---------------- f32x2 packed FMA helpers ------------------------------------
__device__ __forceinline__ unsigned long long dupf(float x) {
    unsigned long long d;
    unsigned int xi = __float_as_uint(x);
    asm("mov.b64 %0, {%1, %1};" : "=l"(d) : "r"(xi));
    return d;
}
__device__ __forceinline__ void fma2(unsigned long long& acc,
                                     unsigned long long a, unsigned long long b) {
    asm("fma.rn.f32x2 %0, %1, %2, %0;" : "+l"(acc) : "l"(a), "l"(b));
}
__device__ __forceinline__ float2 unpk(unsigned long long v) {
    float2 f;
    asm("mov.b64 {%0, %1}, %2;" : "=f"(f.x), "=f"(f.y) : "l"(v));
    return f;
}

// ---------------- helpers ----------------------------------------------------
__device__ __forceinline__ int lower_bound_i(const int* __restrict__ a, int n, int key) {
    int lo = 0, hi = n;
    while (lo < hi) {
        int mid = (lo + hi) >> 1;
        if (a[mid] < key) lo = mid + 1; else hi = mid;
    }
    return lo;
}

__global__ void k_node_off(const int* __restrict__ src) {
    int v = blockIdx.x * blockDim.x + threadIdx.x;
    if (v <= NND) g_noff[v] = lower_bound_i(src, NNZE, v);
}

__global__ void k_graph_off(const int* __restrict__ batch) {
    int g = threadIdx.x;
    if (g <= NGR) g_goff[g] = lower_bound_i(batch, NND, g);
}

__global__ void k_zero_cnt() {
    int i = blockIdx.x * blockDim.x + threadIdx.x;
    if (i < NED) g_ecnt[i] = 0;
}
__global__ void k_hist(const int* __restrict__ dst) {
    int i = blockIdx.x * blockDim.x + threadIdx.x;
    if (i < NNZE) atomicAdd(&g_ecnt[dst[i]], 1);
}

// ---------------- 4x8 register-tiled GEMM with packed f32x2 -------------------
// block (8,16): tx covers 64 cols (4 f32x2 pairs), ty*4+r covers 64 rows
__device__ __forceinline__ void gemm48(const float* __restrict__ xs,
                                       const float* __restrict__ Ws,
                                       unsigned long long acc[4][4], int tx, int ty) {
    #pragma unroll 4
    for (int k = 0; k < 64; k += 4) {
        ulonglong2 w2[4][2];
        #pragma unroll
        for (int kk = 0; kk < 4; kk++) {
            w2[kk][0] = *reinterpret_cast<const ulonglong2*>(&Ws[(k + kk) * 64 + tx * 8]);
            w2[kk][1] = *reinterpret_cast<const ulonglong2*>(&Ws[(k + kk) * 64 + tx * 8 + 4]);
        }
        #pragma unroll
        for (int r = 0; r < 4; r++) {
            float xv[4];
            *reinterpret_cast<float4*>(xv) =
                *reinterpret_cast<const float4*>(&xs[(ty * 4 + r) * XSTR + k]);
            #pragma unroll
            for (int kk = 0; kk < 4; kk++) {
                unsigned long long xd = dupf(xv[kk]);
                fma2(acc[r][0], xd, w2[kk][0].x);
                fma2(acc[r][1], xd, w2[kk][0].y);
                fma2(acc[r][2], xd, w2[kk][1].x);
                fma2(acc[r][3], xd, w2[kk][1].y);
            }
        }
    }
}

__device__ __forceinline__ void zero_acc(unsigned long long acc[4][4]) {
    #pragma unroll
    for (int r = 0; r < 4; r++)
        #pragma unroll
        for (int c = 0; c < 4; c++) acc[r][c] = 0ull;
}

// load a 64-row x 64-col tile (row stride 64) into padded shared (128 threads)
__device__ __forceinline__ void load_tile64(float* __restrict__ xs,
                                            const float* __restrict__ g,
                                            int row0, int nrows, int t) {
    #pragma unroll
    for (int i = t; i < 64 * 16; i += 128) {
        int r  = i >> 4;
        int c4 = (i & 15) * 4;
        float4 v = make_float4(0.f, 0.f, 0.f, 0.f);
        int row = row0 + r;
        if (row < nrows) v = *reinterpret_cast<const float4*>(&g[(size_t)row * 64 + c4]);
        *reinterpret_cast<float4*>(&xs[r * XSTR + c4]) = v;
    }
}

// ---------------- input layer: x = relu(X @ W_in + b_in); zero g_esum --------
__global__ void __launch_bounds__(128) k_in(const float* __restrict__ X,
                                            const float* __restrict__ W,
                                            const float* __restrict__ b) {
    __shared__ float Ws[64 * 64];
    __shared__ float xs[64 * XSTR];
    __shared__ float bs[64];
    const int tx = threadIdx.x, ty = threadIdx.y;
    const int t = ty * 8 + tx;
    const int row0 = blockIdx.x * 64;
    if (t < 64) bs[t] = b[t];

    unsigned long long acc[4][4];
    zero_acc(acc);

    for (int ch = 0; ch < 2; ch++) {
        __syncthreads();
        for (int i = t; i < 64 * 64; i += 128) Ws[i] = W[ch * 64 * 64 + i];
        #pragma unroll
        for (int i = t; i < 64 * 16; i += 128) {
            int r = i >> 4, c4 = (i & 15) * 4;
            float4 v = make_float4(0.f, 0.f, 0.f, 0.f);
            int row = row0 + r;
            if (row < NND) v = *reinterpret_cast<const float4*>(&X[(size_t)row * FT + ch * 64 + c4]);
            *reinterpret_cast<float4*>(&xs[r * XSTR + c4]) = v;
        }
        __syncthreads();
        gemm48(xs, Ws, acc, tx, ty);
    }

    #pragma unroll
    for (int r = 0; r < 4; r++) {
        int row = row0 + ty * 4 + r;
        if (row < NND) {
            float o[8];
            #pragma unroll
            for (int p = 0; p < 4; p++) {
                float2 f = unpk(acc[r][p]);
                o[2 * p]     = fmaxf(f.x + bs[tx * 8 + 2 * p],     0.f);
                o[2 * p + 1] = fmaxf(f.y + bs[tx * 8 + 2 * p + 1], 0.f);
            }
            *reinterpret_cast<float4*>(&g_x [(size_t)row * 64 + tx * 8])     = *reinterpret_cast<float4*>(&o[0]);
            *reinterpret_cast<float4*>(&g_x [(size_t)row * 64 + tx * 8 + 4]) = *reinterpret_cast<float4*>(&o[4]);
            *reinterpret_cast<float4*>(&g_x0[(size_t)row * 64 + tx * 8])     = *reinterpret_cast<float4*>(&o[0]);
            *reinterpret_cast<float4*>(&g_x0[(size_t)row * 64 + tx * 8 + 4]) = *reinterpret_cast<float4*>(&o[4]);
        }
    }

    // zero g_esum (grid-stride float4): ready for first layer's scatter
    const int gt = blockIdx.x * 128 + t;
    const float4 z4 = make_float4(0.f, 0.f, 0.f, 0.f);
    for (int i = gt; i < NED * 16; i += NB_N * 128)
        *reinterpret_cast<float4*>(&g_esum[i * 4]) = z4;
}

// ---------------- h GEMM + fused V->E scatter ---------------------------------
// h = relu(x@W1a+b1a) @ W1b + b1b (tile kept in shared), then
// for each incidence (s,d) with s in this tile: red g_esum[d] += h[s]
__global__ void __launch_bounds__(128) k_h_sc(const float* __restrict__ Wa,
                                              const float* __restrict__ ba,
                                              const float* __restrict__ Wb,
                                              const float* __restrict__ bb,
                                              const int* __restrict__ src,
                                              const int* __restrict__ dst) {
    __shared__ float Ws[64 * 64];
    __shared__ float xs[64 * XSTR];
    __shared__ float bas[64], bbs[64];
    const int tx = threadIdx.x, ty = threadIdx.y;
    const int t = ty * 8 + tx;
    const int row0 = blockIdx.x * 64;
    for (int i = t; i < 64 * 64; i += 128) Ws[i] = Wa[i];
    if (t < 64) { bas[t] = ba[t]; bbs[t] = bb[t]; }
    load_tile64(xs, g_x, row0, NND, t);
    __syncthreads();

    unsigned long long acc[4][4];
    zero_acc(acc);
    gemm48(xs, Ws, acc, tx, ty);
    __syncthreads();

    // tm = relu(acc + ba) back into xs; reload Ws with Wb
    #pragma unroll
    for (int r = 0; r < 4; r++)
        #pragma unroll
        for (int p = 0; p < 4; p++) {
            float2 f = unpk(acc[r][p]);
            xs[(ty * 4 + r) * XSTR + tx * 8 + 2 * p]     = fmaxf(f.x + bas[tx * 8 + 2 * p],     0.f);
            xs[(ty * 4 + r) * XSTR + tx * 8 + 2 * p + 1] = fmaxf(f.y + bas[tx * 8 + 2 * p + 1], 0.f);
        }
    for (int i = t; i < 64 * 64; i += 128) Ws[i] = Wb[i];
    __syncthreads();

    unsigned long long acc2[4][4];
    zero_acc(acc2);
    gemm48(xs, Ws, acc2, tx, ty);
    __syncthreads();                  // xs reads done; overwrite with h

    #pragma unroll
    for (int r = 0; r < 4; r++)
        #pragma unroll
        for (int p = 0; p < 4; p++) {
            float2 f = unpk(acc2[r][p]);
            xs[(ty * 4 + r) * XSTR + tx * 8 + 2 * p]     = f.x + bbs[tx * 8 + 2 * p];
            xs[(ty * 4 + r) * XSTR + tx * 8 + 2 * p + 1] = f.y + bbs[tx * 8 + 2 * p + 1];
        }
    __syncthreads();

    // scatter: incidences with src in [row0, row0+64)
    const int jbeg = g_noff[row0];
    const int jend = g_noff[min(row0 + 64, NND)];
    const int work = (jend - jbeg) * 16;
    const int q4 = (t & 15) * 4;               // fixed per thread (stride 128 % 16 == 0)
    for (int idx = t; idx < work; idx += 128) {
        const int j = jbeg + (idx >> 4);
        const int s = __ldg(&src[j]) - row0;
        const int d = __ldg(&dst[j]);
        const float4 v = *reinterpret_cast<const float4*>(&xs[s * XSTR + q4]);
        float* p = &g_esum[(size_t)d * 64 + q4];
        asm volatile("red.global.add.v4.f32 [%0], {%1,%2,%3,%4};"
                     :: "l"(p), "f"(v.x), "f"(v.y), "f"(v.z), "f"(v.w) : "memory");
    }
}

// ---------------- Y = (esum / max(cnt,1)) @ W2b; re-zero esum -----------------
__global__ void __launch_bounds__(128) k_y(const float* __restrict__ W2) {
    __shared__ float Ws[64 * 64];
    __shared__ float xs[64 * XSTR];
    __shared__ float cs[64];
    const int tx = threadIdx.x, ty = threadIdx.y;
    const int t = ty * 8 + tx;
    const int row0 = blockIdx.x * 64;
    for (int i = t; i < 64 * 64; i += 128) Ws[i] = W2[64 * 64 + i];   // W2b
    if (t < 64) {
        int row = row0 + t;
        int c = (row < NED) ? g_ecnt[row] : 1;
        cs[t] = 1.f / fmaxf((float)c, 1.f);
    }
    // load tile + re-zero the global rows we consumed (same thread, same addrs)
    const float4 z4 = make_float4(0.f, 0.f, 0.f, 0.f);
    #pragma unroll
    for (int i = t; i < 64 * 16; i += 128) {
        int r = i >> 4, c4 = (i & 15) * 4;
        float4 v = z4;
        int row = row0 + r;
        if (row < NED) {
            v = *reinterpret_cast<const float4*>(&g_esum[(size_t)row * 64 + c4]);
            *reinterpret_cast<float4*>(&g_esum[(size_t)row * 64 + c4]) = z4;
        }
        *reinterpret_cast<float4*>(&xs[r * XSTR + c4]) = v;
    }
    __syncthreads();

    // scale rows by 1/cnt in place
    #pragma unroll
    for (int i = t; i < 64 * 16; i += 128) {
        int r = i >> 4, c4 = (i & 15) * 4;
        float inv = cs[r];
        float4 v = *reinterpret_cast<float4*>(&xs[r * XSTR + c4]);
        v.x *= inv; v.y *= inv; v.z *= inv; v.w *= inv;
        *reinterpret_cast<float4*>(&xs[r * XSTR + c4]) = v;
    }
    __syncthreads();

    unsigned long long acc[4][4];
    zero_acc(acc);
    gemm48(xs, Ws, acc, tx, ty);

    #pragma unroll
    for (int r = 0; r < 4; r++) {
        int row = row0 + ty * 4 + r;
        if (row < NED) {
            float o[8];
            #pragma unroll
            for (int p = 0; p < 4; p++) {
                float2 f = unpk(acc[r][p]);
                o[2 * p] = f.x; o[2 * p + 1] = f.y;
            }
            *reinterpret_cast<float4*>(&g_y[(size_t)row * 64 + tx * 8])     = *reinterpret_cast<float4*>(&o[0]);
            *reinterpret_cast<float4*>(&g_y[(size_t)row * 64 + tx * 8 + 4]) = *reinterpret_cast<float4*>(&o[4]);
        }
    }
}

// ---------------- combine: Xv = x@W2a + b2 + mean_j Y[dst_j]; residual; W3; relu
__global__ void __launch_bounds__(128) k_combine(const float* __restrict__ W2,
                                                 const float* __restrict__ b2,
                                                 const float* __restrict__ W3,
                                                 const float* __restrict__ b3,
                                                 const int* __restrict__ dst) {
    __shared__ float Ws[64 * 64];
    __shared__ float xs[64 * XSTR];
    __shared__ float b2s[64], b3s[64];
    __shared__ int offs[65];
    const int tx = threadIdx.x, ty = threadIdx.y;
    const int t = ty * 8 + tx;
    const int row0 = blockIdx.x * 64;
    for (int i = t; i < 64 * 64; i += 128) Ws[i] = W2[i];    // W2a
    if (t < 64) { b2s[t] = b2[t]; b3s[t] = b3[t]; }
    if (t < 65) offs[t] = g_noff[min(row0 + t, NND)];
    load_tile64(xs, g_x, row0, NND, t);
    __syncthreads();

    unsigned long long acc[4][4];
    zero_acc(acc);
    gemm48(xs, Ws, acc, tx, ty);         // x @ W2a
    __syncthreads();                     // xs free

    // gather mean of Y over node's edges (unroll 2 for MLP), compose u into xs
    #pragma unroll
    for (int r = 0; r < 4; r++) {
        const int lr = ty * 4 + r;
        const int v = row0 + lr;
        float z0[8], z1[8];
        #pragma unroll
        for (int c = 0; c < 8; c++) { z0[c] = 0.f; z1[c] = 0.f; }
        int cnt = 0;
        if (v < NND) {
            const int beg = offs[lr], end = offs[lr + 1];
            cnt = end - beg;
            int j = beg;
            for (; j + 1 < end; j += 2) {
                const int d0 = __ldg(&dst[j]);
                const int d1 = __ldg(&dst[j + 1]);
                const float4 a0 = *reinterpret_cast<const float4*>(&g_y[(size_t)d0 * 64 + tx * 8]);
                const float4 b0 = *reinterpret_cast<const float4*>(&g_y[(size_t)d0 * 64 + tx * 8 + 4]);
                const float4 a1 = *reinterpret_cast<const float4*>(&g_y[(size_t)d1 * 64 + tx * 8]);
                const float4 b1 = *reinterpret_cast<const float4*>(&g_y[(size_t)d1 * 64 + tx * 8 + 4]);
                z0[0] += a0.x; z0[1] += a0.y; z0[2] += a0.z; z0[3] += a0.w;
                z0[4] += b0.x; z0[5] += b0.y; z0[6] += b0.z; z0[7] += b0.w;
                z1[0] += a1.x; z1[1] += a1.y; z1[2] += a1.z; z1[3] += a1.w;
                z1[4] += b1.x; z1[5] += b1.y; z1[6] += b1.z; z1[7] += b1.w;
            }
            if (j < end) {
                const int d = __ldg(&dst[j]);
                const float4 a = *reinterpret_cast<const float4*>(&g_y[(size_t)d * 64 + tx * 8]);
                const float4 b = *reinterpret_cast<const float4*>(&g_y[(size_t)d * 64 + tx * 8 + 4]);
                z0[0] += a.x; z0[1] += a.y; z0[2] += a.z; z0[3] += a.w;
                z0[4] += b.x; z0[5] += b.y; z0[6] += b.z; z0[7] += b.w;
            }
        }
        const float inv = (cnt > 0) ? 1.f / (float)cnt : 0.f;
        float x0a[8] = {0.f, 0.f, 0.f, 0.f, 0.f, 0.f, 0.f, 0.f};
        if (v < NND) {
            *reinterpret_cast<float4*>(&x0a[0]) = *reinterpret_cast<const float4*>(&g_x0[(size_t)v * 64 + tx * 8]);
            *reinterpret_cast<float4*>(&x0a[4]) = *reinterpret_cast<const float4*>(&g_x0[(size_t)v * 64 + tx * 8 + 4]);
        }
        #pragma unroll
        for (int p = 0; p < 4; p++) {
            float2 f = unpk(acc[r][p]);
            float a2[2] = {f.x, f.y};
            #pragma unroll
            for (int hh = 0; hh < 2; hh++) {
                const int c = 2 * p + hh;
                float xv = 0.f;
                if (cnt > 0) xv = a2[hh] + b2s[tx * 8 + c] + (z0[c] + z1[c]) * inv;
                xs[lr * XSTR + tx * 8 + c] = 0.5f * xv + 0.5f * x0a[c];
            }
        }
    }
    for (int i = t; i < 64 * 64; i += 128) Ws[i] = W3[i];
    __syncthreads();

    unsigned long long acc2[4][4];
    zero_acc(acc2);
    gemm48(xs, Ws, acc2, tx, ty);

    #pragma unroll
    for (int r = 0; r < 4; r++) {
        int row = row0 + ty * 4 + r;
        if (row < NND) {
            float o[8];
            #pragma unroll
            for (int p = 0; p < 4; p++) {
                float2 f = unpk(acc2[r][p]);
                o[2 * p]     = fmaxf(f.x + b3s[tx * 8 + 2 * p],     0.f);
                o[2 * p + 1] = fmaxf(f.y + b3s[tx * 8 + 2 * p + 1], 0.f);
            }
            *reinterpret_cast<float4*>(&g_x[(size_t)row * 64 + tx * 8])     = *reinterpret_cast<float4*>(&o[0]);
            *reinterpret_cast<float4*>(&g_x[(size_t)row * 64 + tx * 8 + 4]) = *reinterpret_cast<float4*>(&o[4]);
        }
    }
}

// ---------------- classifier: cls = relu(x@Wc1+bc1) @ Wc2 + bc2 ---------------
__global__ void __launch_bounds__(128) k_cls(const float* __restrict__ W1,
                                             const float* __restrict__ b1,
                                             const float* __restrict__ W2,
                                             const float* __restrict__ b2) {
    __shared__ float W1s[64 * 64];
    __shared__ float W2s[64 * 32];
    __shared__ float xs[64 * XSTR];
    __shared__ float b1s[64], b2s[32];
    const int tx = threadIdx.x, ty = threadIdx.y;
    const int t = ty * 8 + tx;
    const int row0 = blockIdx.x * 64;
    for (int i = t; i < 64 * 64; i += 128) W1s[i] = W1[i];
    for (int i = t; i < 64 * 32; i += 128) W2s[i] = W2[i];
    if (t < 64) b1s[t] = b1[t];
    if (t < 32) b2s[t] = b2[t];
    load_tile64(xs, g_x, row0, NND, t);
    __syncthreads();

    unsigned long long acc[4][4];
    zero_acc(acc);
    gemm48(xs, W1s, acc, tx, ty);
    __syncthreads();
    #pragma unroll
    for (int r = 0; r < 4; r++)
        #pragma unroll
        for (int p = 0; p < 4; p++) {
            float2 f = unpk(acc[r][p]);
            xs[(ty * 4 + r) * XSTR + tx * 8 + 2 * p]     = fmaxf(f.x + b1s[tx * 8 + 2 * p],     0.f);
            xs[(ty * 4 + r) * XSTR + tx * 8 + 2 * p + 1] = fmaxf(f.y + b1s[tx * 8 + 2 * p + 1], 0.f);
        }
    __syncthreads();

    // GEMM2: 64 -> 32, 4 rows x 4 cols (2 f32x2 pairs) per thread
    unsigned long long acc2[4][2];
    #pragma unroll
    for (int r = 0; r < 4; r++) { acc2[r][0] = 0ull; acc2[r][1] = 0ull; }
    #pragma unroll 4
    for (int k = 0; k < 64; k += 4) {
        ulonglong2 w2[4];
        #pragma unroll
        for (int kk = 0; kk < 4; kk++)
            w2[kk] = *reinterpret_cast<const ulonglong2*>(&W2s[(k + kk) * 32 + tx * 4]);
        #pragma unroll
        for (int r = 0; r < 4; r++) {
            float xv[4];
            *reinterpret_cast<float4*>(xv) =
                *reinterpret_cast<const float4*>(&xs[(ty * 4 + r) * XSTR + k]);
            #pragma unroll
            for (int kk = 0; kk < 4; kk++) {
                unsigned long long xd = dupf(xv[kk]);
                fma2(acc2[r][0], xd, w2[kk].x);
                fma2(acc2[r][1], xd, w2[kk].y);
            }
        }
    }
    #pragma unroll
    for (int r = 0; r < 4; r++) {
        int row = row0 + ty * 4 + r;
        if (row < NND) {
            float o[4];
            float2 f0 = unpk(acc2[r][0]);
            float2 f1 = unpk(acc2[r][1]);
            o[0] = f0.x + b2s[tx * 4 + 0];
            o[1] = f0.y + b2s[tx * 4 + 1];
            o[2] = f1.x + b2s[tx * 4 + 2];
            o[3] = f1.y + b2s[tx * 4 + 3];
            *reinterpret_cast<float4*>(&g_cls[(size_t)row * 32 + tx * 4]) = *reinterpret_cast<float4*>(o);
        }
    }
}

// ---------------- readout: per-graph mean over sorted all_batch ---------------
__global__ void k_readout(float* __restrict__ out) {
    __shared__ float part[8][NCLS];
    const int g = blockIdx.x;
    const int tx = threadIdx.x, ty = threadIdx.y;  // (32, 8)
    const int beg = g_goff[g], end = g_goff[g + 1];
    float s = 0.f;
    for (int j = beg + ty; j < end; j += 8)
        s += g_cls[(size_t)j * NCLS + tx];
    part[ty][tx] = s;
    __syncthreads();
    if (ty == 0) {
        float tot = 0.f;
        #pragma unroll
        for (int r = 0; r < 8; r++) tot += part[r][tx];
        const int c = end - beg;
        out[g * NCLS + tx] = tot / fmaxf((float)c, 1.f);
    }
}

// ---------------- launch ------------------------------------------------------
extern "C" void kernel_launch(void* const* d_in, const int* in_sizes, int n_in,
                              void* d_out, int out_size) {
    const float* X       = (const float*)d_in[0];
    const int*   v2e_src = (const int*)  d_in[1];
    const int*   v2e_dst = (const int*)  d_in[2];
    const int*   batch   = (const int*)  d_in[3];
    const float* W_in    = (const float*)d_in[4];
    const float* b_in    = (const float*)d_in[5];
    const float* W1a     = (const float*)d_in[6];
    const float* b1a     = (const float*)d_in[7];
    const float* W1b     = (const float*)d_in[8];
    const float* b1b     = (const float*)d_in[9];
    const float* W2      = (const float*)d_in[10];
    const float* b2      = (const float*)d_in[11];
    const float* W3      = (const float*)d_in[12];
    const float* b3      = (const float*)d_in[13];
    const float* Wc1     = (const float*)d_in[14];
    const float* bc1     = (const float*)d_in[15];
    const float* Wc2     = (const float*)d_in[16];
    const float* bc2     = (const float*)d_in[17];
    float* out = (float*)d_out;

    const dim3 blk(8, 16);

    // once per launch
    k_node_off<<<(NND + 1 + 255) / 256, 256>>>(v2e_src);
    k_graph_off<<<1, NGR + 1>>>(batch);
    k_zero_cnt<<<(NED + 255) / 256, 256>>>();
    k_hist<<<(NNZE + 255) / 256, 256>>>(v2e_dst);

    k_in<<<NB_N, blk>>>(X, W_in, b_in);   // also zeroes g_esum

    for (int layer = 0; layer < 2; layer++) {
        k_h_sc<<<NB_N, blk>>>(W1a, b1a, W1b, b1b, v2e_src, v2e_dst);
        k_y<<<NB_E, blk>>>(W2);           // also re-zeroes g_esum tiles
        k_combine<<<NB_N, blk>>>(W2, b2, W3, b3, v2e_dst);
    }

    k_cls<<<NB_N, blk>>>(Wc1, bc1, Wc2, bc2);
    k_readout<<<NGR, dim3(32, 8)>>>(out);
}

// round 5
// speedup vs baseline: 1.1216x; 1.1216x over previous
#include <cuda_runtime.h>
#include <cuda_bf16.h>

// Problem constants (fixed by the reference)
#define NND   100000      // nodes
#define NED   50000       // hyperedges
#define NNZE  1280000     // incidence nnz
#define FT    128
#define HID   64
#define NCLS  32
#define NGR   256

#define XSTR  68          // padded shared row stride (floats)
#define NB_N  1563        // ceil(NND/64)
#define NB_E  782         // ceil(NED/64)

// ---------------- device scratch (static; no allocation allowed) -------------
__device__ float g_x   [NND * HID];
__device__ float g_x0  [NND * HID];
__device__ float g_h   [NND * HID];
__device__ float g_esum[NED * HID];
__device__ int   g_ecnt[NED];
__device__ float g_y   [NED * HID];
__device__ float g_cls [NND * NCLS];
__device__ int   g_noff[NND + 1];
__device__ int   g_goff[NGR + 1];

// ---------------- f32x2 packed FMA helpers ------------------------------------
__device__ __forceinline__ unsigned long long dupf(float x) {
    unsigned long long d;
    unsigned int xi = __float_as_uint(x);
    asm("mov.b64 %0, {%1, %1};" : "=l"(d) : "r"(xi));
    return d;
}
__device__ __forceinline__ void fma2(unsigned long long& acc,
                                     unsigned long long a, unsigned long long b) {
    asm("fma.rn.f32x2 %0, %1, %2, %0;" : "+l"(acc) : "l"(a), "l"(b));
}
__device__ __forceinline__ float2 unpk(unsigned long long v) {
    float2 f;
    asm("mov.b64 {%0, %1}, %2;" : "=f"(f.x), "=f"(f.y) : "l"(v));
    return f;
}

// ---------------- helpers ----------------------------------------------------
__device__ __forceinline__ int lower_bound_i(const int* __restrict__ a, int n, int key) {
    int lo = 0, hi = n;
    while (lo < hi) {
        int mid = (lo + hi) >> 1;
        if (a[mid] < key) lo = mid + 1; else hi = mid;
    }
    return lo;
}

__global__ void k_node_off(const int* __restrict__ src) {
    int v = blockIdx.x * blockDim.x + threadIdx.x;
    if (v <= NND) g_noff[v] = lower_bound_i(src, NNZE, v);
}

__global__ void k_graph_off(const int* __restrict__ batch) {
    int g = threadIdx.x;
    if (g <= NGR) g_goff[g] = lower_bound_i(batch, NND, g);
}

__global__ void k_zero_cnt() {
    int i = blockIdx.x * blockDim.x + threadIdx.x;
    if (i < NED) g_ecnt[i] = 0;
}
__global__ void k_hist(const int* __restrict__ dst) {
    int i = blockIdx.x * blockDim.x + threadIdx.x;
    if (i < NNZE) atomicAdd(&g_ecnt[dst[i]], 1);
}

// ---- 4x4 register-tiled GEMM over a 64-row tile, packed f32x2 ----------------
// block (16,16): tx covers 64 cols (2 f32x2 pairs each), ty*4+r covers 64 rows
__device__ __forceinline__ void gemm_tile(const float* __restrict__ xs,
                                          const float* __restrict__ Ws,
                                          unsigned long long acc[4][2],
                                          int tx, int ty) {
    #pragma unroll 4
    for (int k = 0; k < 64; k += 4) {
        ulonglong2 w2[4];
        #pragma unroll
        for (int kk = 0; kk < 4; kk++)
            w2[kk] = *reinterpret_cast<const ulonglong2*>(&Ws[(k + kk) * 64 + tx * 4]);
        #pragma unroll
        for (int r = 0; r < 4; r++) {
            float xv[4];
            *reinterpret_cast<float4*>(xv) =
                *reinterpret_cast<const float4*>(&xs[(ty * 4 + r) * XSTR + k]);
            #pragma unroll
            for (int kk = 0; kk < 4; kk++) {
                unsigned long long xd = dupf(xv[kk]);
                fma2(acc[r][0], xd, w2[kk].x);
                fma2(acc[r][1], xd, w2[kk].y);
            }
        }
    }
}

__device__ __forceinline__ void zero_acc(unsigned long long acc[4][2]) {
    #pragma unroll
    for (int r = 0; r < 4; r++) { acc[r][0] = 0ull; acc[r][1] = 0ull; }
}

// load a 64-row x 64-col tile (row-major, stride 64) into padded shared
__device__ __forceinline__ void load_tile64(float* __restrict__ xs,
                                            const float* __restrict__ g,
                                            int row0, int nrows, int t) {
    #pragma unroll
    for (int i = t; i < 64 * 16; i += 256) {
        int r  = i >> 4;
        int c4 = (i & 15) * 4;
        float4 v = make_float4(0.f, 0.f, 0.f, 0.f);
        int row = row0 + r;
        if (row < nrows) v = *reinterpret_cast<const float4*>(&g[(size_t)row * 64 + c4]);
        *reinterpret_cast<float4*>(&xs[r * XSTR + c4]) = v;
    }
}

// ---------------- input layer: x = relu(X @ W_in + b_in); zero g_esum --------
__global__ void __launch_bounds__(256) k_in(const float* __restrict__ X,
                                            const float* __restrict__ W,
                                            const float* __restrict__ b) {
    __shared__ float Ws[64 * 64];
    __shared__ float xs[64 * XSTR];
    __shared__ float bs[64];
    const int tx = threadIdx.x, ty = threadIdx.y;
    const int t = ty * 16 + tx;
    const int row0 = blockIdx.x * 64;
    if (t < 64) bs[t] = b[t];

    unsigned long long acc[4][2];
    zero_acc(acc);

    for (int ch = 0; ch < 2; ch++) {
        __syncthreads();
        for (int i = t; i < 64 * 64; i += 256) Ws[i] = W[ch * 64 * 64 + i];
        #pragma unroll
        for (int i = t; i < 64 * 16; i += 256) {
            int r = i >> 4, c4 = (i & 15) * 4;
            float4 v = make_float4(0.f, 0.f, 0.f, 0.f);
            int row = row0 + r;
            if (row < NND) v = *reinterpret_cast<const float4*>(&X[(size_t)row * FT + ch * 64 + c4]);
            *reinterpret_cast<float4*>(&xs[r * XSTR + c4]) = v;
        }
        __syncthreads();
        gemm_tile(xs, Ws, acc, tx, ty);
    }

    #pragma unroll
    for (int r = 0; r < 4; r++) {
        int row = row0 + ty * 4 + r;
        if (row < NND) {
            float2 f0 = unpk(acc[r][0]);
            float2 f1 = unpk(acc[r][1]);
            float4 o;
            o.x = fmaxf(f0.x + bs[tx * 4 + 0], 0.f);
            o.y = fmaxf(f0.y + bs[tx * 4 + 1], 0.f);
            o.z = fmaxf(f1.x + bs[tx * 4 + 2], 0.f);
            o.w = fmaxf(f1.y + bs[tx * 4 + 3], 0.f);
            *reinterpret_cast<float4*>(&g_x [(size_t)row * 64 + tx * 4]) = o;
            *reinterpret_cast<float4*>(&g_x0[(size_t)row * 64 + tx * 4]) = o;
        }
    }

    // zero g_esum for the first layer's scatter
    const int gt = blockIdx.x * 256 + t;
    const float4 z4 = make_float4(0.f, 0.f, 0.f, 0.f);
    for (int i = gt; i < NED * 16; i += NB_N * 256)
        *reinterpret_cast<float4*>(&g_esum[i * 4]) = z4;
}

// ---------------- h = relu(x@W1a+b1a) @ W1b + b1b ----------------------------
__global__ void __launch_bounds__(256) k_h(const float* __restrict__ Wa,
                                           const float* __restrict__ ba,
                                           const float* __restrict__ Wb,
                                           const float* __restrict__ bb) {
    __shared__ float Ws[64 * 64];
    __shared__ float xs[64 * XSTR];
    __shared__ float bas[64], bbs[64];
    const int tx = threadIdx.x, ty = threadIdx.y;
    const int t = ty * 16 + tx;
    const int row0 = blockIdx.x * 64;
    for (int i = t; i < 64 * 64; i += 256) Ws[i] = Wa[i];
    if (t < 64) { bas[t] = ba[t]; bbs[t] = bb[t]; }
    load_tile64(xs, g_x, row0, NND, t);
    __syncthreads();

    unsigned long long acc[4][2];
    zero_acc(acc);
    gemm_tile(xs, Ws, acc, tx, ty);
    __syncthreads();

    // tm = relu(acc + ba) back into xs; reload Ws with Wb
    #pragma unroll
    for (int r = 0; r < 4; r++) {
        float2 f0 = unpk(acc[r][0]);
        float2 f1 = unpk(acc[r][1]);
        xs[(ty * 4 + r) * XSTR + tx * 4 + 0] = fmaxf(f0.x + bas[tx * 4 + 0], 0.f);
        xs[(ty * 4 + r) * XSTR + tx * 4 + 1] = fmaxf(f0.y + bas[tx * 4 + 1], 0.f);
        xs[(ty * 4 + r) * XSTR + tx * 4 + 2] = fmaxf(f1.x + bas[tx * 4 + 2], 0.f);
        xs[(ty * 4 + r) * XSTR + tx * 4 + 3] = fmaxf(f1.y + bas[tx * 4 + 3], 0.f);
    }
    for (int i = t; i < 64 * 64; i += 256) Ws[i] = Wb[i];
    __syncthreads();

    unsigned long long acc2[4][2];
    zero_acc(acc2);
    gemm_tile(xs, Ws, acc2, tx, ty);

    #pragma unroll
    for (int r = 0; r < 4; r++) {
        int row = row0 + ty * 4 + r;
        if (row < NND) {
            float2 f0 = unpk(acc2[r][0]);
            float2 f1 = unpk(acc2[r][1]);
            float4 o;
            o.x = f0.x + bbs[tx * 4 + 0];
            o.y = f0.y + bbs[tx * 4 + 1];
            o.z = f1.x + bbs[tx * 4 + 2];
            o.w = f1.y + bbs[tx * 4 + 3];
            *reinterpret_cast<float4*>(&g_h[(size_t)row * 64 + tx * 4]) = o;
        }
    }
}

// ---------------- V->E scatter: esum[dst] += h[src] ---------------------------
__global__ void k_scatter(const int* __restrict__ src, const int* __restrict__ dst) {
    const int tot = NNZE * 16;   // 16 float4 lanes per nnz row
    for (int idx = blockIdx.x * blockDim.x + threadIdx.x; idx < tot;
         idx += gridDim.x * blockDim.x) {
        const int i = idx >> 4;
        const int q = idx & 15;
        const int s = __ldg(&src[i]);
        const int d = __ldg(&dst[i]);
        const float4 v = *reinterpret_cast<const float4*>(&g_h[(size_t)s * HID + q * 4]);
        float* p = &g_esum[(size_t)d * HID + q * 4];
        asm volatile("red.global.add.v4.f32 [%0], {%1,%2,%3,%4};"
                     :: "l"(p), "f"(v.x), "f"(v.y), "f"(v.z), "f"(v.w) : "memory");
    }
}

// ---------------- Y = (esum / max(cnt,1)) @ W2b; re-zero esum -----------------
__global__ void __launch_bounds__(256) k_y(const float* __restrict__ W2) {
    __shared__ float Ws[64 * 64];
    __shared__ float xs[64 * XSTR];
    __shared__ float cs[64];
    const int tx = threadIdx.x, ty = threadIdx.y;
    const int t = ty * 16 + tx;
    const int row0 = blockIdx.x * 64;
    for (int i = t; i < 64 * 64; i += 256) Ws[i] = W2[64 * 64 + i];   // W2b
    if (t < 64) {
        int row = row0 + t;
        int c = (row < NED) ? g_ecnt[row] : 1;
        cs[t] = 1.f / fmaxf((float)c, 1.f);
    }
    // load tile and re-zero the consumed rows (ready for next layer's scatter)
    const float4 z4 = make_float4(0.f, 0.f, 0.f, 0.f);
    #pragma unroll
    for (int i = t; i < 64 * 16; i += 256) {
        int r = i >> 4, c4 = (i & 15) * 4;
        float4 v = z4;
        int row = row0 + r;
        if (row < NED) {
            v = *reinterpret_cast<const float4*>(&g_esum[(size_t)row * 64 + c4]);
            *reinterpret_cast<float4*>(&g_esum[(size_t)row * 64 + c4]) = z4;
        }
        *reinterpret_cast<float4*>(&xs[r * XSTR + c4]) = v;
    }
    __syncthreads();

    // scale rows by 1/cnt in place
    #pragma unroll
    for (int i = t; i < 64 * 16; i += 256) {
        int r = i >> 4, c4 = (i & 15) * 4;
        float inv = cs[r];
        float4 v = *reinterpret_cast<float4*>(&xs[r * XSTR + c4]);
        v.x *= inv; v.y *= inv; v.z *= inv; v.w *= inv;
        *reinterpret_cast<float4*>(&xs[r * XSTR + c4]) = v;
    }
    __syncthreads();

    unsigned long long acc[4][2];
    zero_acc(acc);
    gemm_tile(xs, Ws, acc, tx, ty);

    #pragma unroll
    for (int r = 0; r < 4; r++) {
        int row = row0 + ty * 4 + r;
        if (row < NED) {
            float2 f0 = unpk(acc[r][0]);
            float2 f1 = unpk(acc[r][1]);
            float4 o = make_float4(f0.x, f0.y, f1.x, f1.y);
            *reinterpret_cast<float4*>(&g_y[(size_t)row * 64 + tx * 4]) = o;
        }
    }
}

// ---------------- combine: Xv = x@W2a + b2 + mean_j Y[dst_j]; residual; W3; relu
__global__ void __launch_bounds__(256) k_combine(const float* __restrict__ W2,
                                                 const float* __restrict__ b2,
                                                 const float* __restrict__ W3,
                                                 const float* __restrict__ b3,
                                                 const int* __restrict__ dst) {
    __shared__ float Ws[64 * 64];
    __shared__ float xs[64 * XSTR];
    __shared__ float b2s[64], b3s[64];
    __shared__ int offs[65];
    const int tx = threadIdx.x, ty = threadIdx.y;
    const int t = ty * 16 + tx;
    const int row0 = blockIdx.x * 64;
    for (int i = t; i < 64 * 64; i += 256) Ws[i] = W2[i];    // W2a
    if (t < 64) { b2s[t] = b2[t]; b3s[t] = b3[t]; }
    if (t < 65) offs[t] = g_noff[min(row0 + t, NND)];
    load_tile64(xs, g_x, row0, NND, t);
    __syncthreads();

    unsigned long long acc[4][2];
    zero_acc(acc);
    gemm_tile(xs, Ws, acc, tx, ty);

    // gather z[r][0..3] = sum_j Y[dst_j][tx*4 .. tx*4+3]
    float z[4][4];
    #pragma unroll
    for (int r = 0; r < 4; r++)
        #pragma unroll
        for (int c = 0; c < 4; c++) z[r][c] = 0.f;
    #pragma unroll
    for (int r = 0; r < 4; r++) {
        const int lr = ty * 4 + r;
        const int v = row0 + lr;
        if (v < NND) {
            const int beg = offs[lr], end = offs[lr + 1];
            for (int j = beg; j < end; j++) {
                const int d = __ldg(&dst[j]);
                const float4 yv = *reinterpret_cast<const float4*>(&g_y[(size_t)d * 64 + tx * 4]);
                z[r][0] += yv.x; z[r][1] += yv.y; z[r][2] += yv.z; z[r][3] += yv.w;
            }
        }
    }
    __syncthreads();   // xs & Ws free

    // reload Ws with W3; compose u into xs
    for (int i = t; i < 64 * 64; i += 256) Ws[i] = W3[i];
    #pragma unroll
    for (int r = 0; r < 4; r++) {
        const int lr = ty * 4 + r;
        const int row = row0 + lr;
        const int cnt = offs[lr + 1] - offs[lr];
        const float inv = (cnt > 0) ? 1.f / (float)cnt : 0.f;
        float4 x0v = make_float4(0.f, 0.f, 0.f, 0.f);
        if (row < NND) x0v = *reinterpret_cast<const float4*>(&g_x0[(size_t)row * 64 + tx * 4]);
        float x0a[4] = {x0v.x, x0v.y, x0v.z, x0v.w};
        float2 f0 = unpk(acc[r][0]);
        float2 f1 = unpk(acc[r][1]);
        float a4[4] = {f0.x, f0.y, f1.x, f1.y};
        #pragma unroll
        for (int c = 0; c < 4; c++) {
            float xv = 0.f;
            if (cnt > 0) xv = a4[c] + b2s[tx * 4 + c] + z[r][c] * inv;
            xs[lr * XSTR + tx * 4 + c] = 0.5f * xv + 0.5f * x0a[c];
        }
    }
    __syncthreads();

    unsigned long long acc2[4][2];
    zero_acc(acc2);
    gemm_tile(xs, Ws, acc2, tx, ty);

    #pragma unroll
    for (int r = 0; r < 4; r++) {
        int row = row0 + ty * 4 + r;
        if (row < NND) {
            float2 f0 = unpk(acc2[r][0]);
            float2 f1 = unpk(acc2[r][1]);
            float4 o;
            o.x = fmaxf(f0.x + b3s[tx * 4 + 0], 0.f);
            o.y = fmaxf(f0.y + b3s[tx * 4 + 1], 0.f);
            o.z = fmaxf(f1.x + b3s[tx * 4 + 2], 0.f);
            o.w = fmaxf(f1.y + b3s[tx * 4 + 3], 0.f);
            *reinterpret_cast<float4*>(&g_x[(size_t)row * 64 + tx * 4]) = o;
        }
    }
}

// ---------------- classifier: cls = relu(x@Wc1+bc1) @ Wc2 + bc2 ---------------
__global__ void __launch_bounds__(256) k_cls(const float* __restrict__ W1,
                                             const float* __restrict__ b1,
                                             const float* __restrict__ W2,
                                             const float* __restrict__ b2) {
    __shared__ float W1s[64 * 64];
    __shared__ float W2s[64 * 32];
    __shared__ float xs[64 * XSTR];
    __shared__ float b1s[64], b2s[32];
    const int tx = threadIdx.x, ty = threadIdx.y;
    const int t = ty * 16 + tx;
    const int row0 = blockIdx.x * 64;
    for (int i = t; i < 64 * 64; i += 256) W1s[i] = W1[i];
    for (int i = t; i < 64 * 32; i += 256) W2s[i] = W2[i];
    if (t < 64) b1s[t] = b1[t];
    if (t < 32) b2s[t] = b2[t];
    load_tile64(xs, g_x, row0, NND, t);
    __syncthreads();

    unsigned long long acc[4][2];
    zero_acc(acc);
    gemm_tile(xs, W1s, acc, tx, ty);
    __syncthreads();
    #pragma unroll
    for (int r = 0; r < 4; r++) {
        float2 f0 = unpk(acc[r][0]);
        float2 f1 = unpk(acc[r][1]);
        xs[(ty * 4 + r) * XSTR + tx * 4 + 0] = fmaxf(f0.x + b1s[tx * 4 + 0], 0.f);
        xs[(ty * 4 + r) * XSTR + tx * 4 + 1] = fmaxf(f0.y + b1s[tx * 4 + 1], 0.f);
        xs[(ty * 4 + r) * XSTR + tx * 4 + 2] = fmaxf(f1.x + b1s[tx * 4 + 2], 0.f);
        xs[(ty * 4 + r) * XSTR + tx * 4 + 3] = fmaxf(f1.y + b1s[tx * 4 + 3], 0.f);
    }
    __syncthreads();

    // GEMM2: 64 -> 32, 4 rows x 2 cols (1 f32x2 pair) per thread
    unsigned long long acc2[4];
    #pragma unroll
    for (int r = 0; r < 4; r++) acc2[r] = 0ull;
    #pragma unroll 4
    for (int k = 0; k < 64; k += 4) {
        unsigned long long w[4];
        #pragma unroll
        for (int kk = 0; kk < 4; kk++)
            w[kk] = *reinterpret_cast<const unsigned long long*>(&W2s[(k + kk) * 32 + tx * 2]);
        #pragma unroll
        for (int r = 0; r < 4; r++) {
            float xv[4];
            *reinterpret_cast<float4*>(xv) =
                *reinterpret_cast<const float4*>(&xs[(ty * 4 + r) * XSTR + k]);
            #pragma unroll
            for (int kk = 0; kk < 4; kk++)
                fma2(acc2[r], dupf(xv[kk]), w[kk]);
        }
    }
    #pragma unroll
    for (int r = 0; r < 4; r++) {
        int row = row0 + ty * 4 + r;
        if (row < NND) {
            float2 f = unpk(acc2[r]);
            float2 o;
            o.x = f.x + b2s[tx * 2 + 0];
            o.y = f.y + b2s[tx * 2 + 1];
            *reinterpret_cast<float2*>(&g_cls[(size_t)row * 32 + tx * 2]) = o;
        }
    }
}

// ---------------- readout: per-graph mean over sorted all_batch ---------------
__global__ void k_readout(float* __restrict__ out) {
    __shared__ float part[8][NCLS];
    const int g = blockIdx.x;
    const int tx = threadIdx.x, ty = threadIdx.y;  // (32, 8)
    const int beg = g_goff[g], end = g_goff[g + 1];
    float s = 0.f;
    for (int j = beg + ty; j < end; j += 8)
        s += g_cls[(size_t)j * NCLS + tx];
    part[ty][tx] = s;
    __syncthreads();
    if (ty == 0) {
        float tot = 0.f;
        #pragma unroll
        for (int r = 0; r < 8; r++) tot += part[r][tx];
        const int c = end - beg;
        out[g * NCLS + tx] = tot / fmaxf((float)c, 1.f);
    }
}

// ---------------- launch ------------------------------------------------------
extern "C" void kernel_launch(void* const* d_in, const int* in_sizes, int n_in,
                              void* d_out, int out_size) {
    const float* X       = (const float*)d_in[0];
    const int*   v2e_src = (const int*)  d_in[1];
    const int*   v2e_dst = (const int*)  d_in[2];
    const int*   batch   = (const int*)  d_in[3];
    const float* W_in    = (const float*)d_in[4];
    const float* b_in    = (const float*)d_in[5];
    const float* W1a     = (const float*)d_in[6];
    const float* b1a     = (const float*)d_in[7];
    const float* W1b     = (const float*)d_in[8];
    const float* b1b     = (const float*)d_in[9];
    const float* W2      = (const float*)d_in[10];
    const float* b2      = (const float*)d_in[11];
    const float* W3      = (const float*)d_in[12];
    const float* b3      = (const float*)d_in[13];
    const float* Wc1     = (const float*)d_in[14];
    const float* bc1     = (const float*)d_in[15];
    const float* Wc2     = (const float*)d_in[16];
    const float* bc2     = (const float*)d_in[17];
    float* out = (float*)d_out;

    const dim3 blk(16, 16);

    // once per launch
    k_node_off<<<(NND + 1 + 255) / 256, 256>>>(v2e_src);
    k_graph_off<<<1, NGR + 1>>>(batch);
    k_zero_cnt<<<(NED + 255) / 256, 256>>>();
    k_hist<<<(NNZE + 255) / 256, 256>>>(v2e_dst);

    k_in<<<NB_N, blk>>>(X, W_in, b_in);   // also zeroes g_esum

    for (int layer = 0; layer < 2; layer++) {
        k_h<<<NB_N, blk>>>(W1a, b1a, W1b, b1b);
        k_scatter<<<4096, 256>>>(v2e_src, v2e_dst);
        k_y<<<NB_E, blk>>>(W2);           // also re-zeroes g_esum tiles
        k_combine<<<NB_N, blk>>>(W2, b2, W3, b3, v2e_dst);
    }

    k_cls<<<NB_N, blk>>>(Wc1, bc1, Wc2, bc2);
    k_readout<<<NGR, dim3(32, 8)>>>(out);
}